// round 1
// baseline (speedup 1.0000x reference)
#include <cuda_runtime.h>
#include <math.h>

#define BN 512
#define TD 2048
#define SD 768
#define HD 128

// Scratch (device globals — no allocations allowed)
__device__ float g_tp[BN*HD];
__device__ float g_sp[BN*HD];
__device__ float g_Ut[BN*HD];
__device__ float g_Vt[BN*HD];
__device__ float g_Us[BN*HD];
__device__ float g_Vs[BN*HD];

// ---------------------------------------------------------------------------
// Init: zero output scalar, seed tp/sp with biases (split-K GEMM accumulates).
// ---------------------------------------------------------------------------
__global__ void init_kernel(const float* __restrict__ bt,
                            const float* __restrict__ bs,
                            float* __restrict__ out, int out_size) {
    int idx = blockIdx.x * blockDim.x + threadIdx.x;
    if (idx < out_size) out[idx] = 0.0f;
    if (idx < BN * HD) {
        int h = idx & (HD - 1);
        g_tp[idx] = bt[h];
        g_sp[idx] = bs[h];
    }
}

// ---------------------------------------------------------------------------
// Split-K GEMM with atomic accumulation into g_tp / g_sp.
// Block: 32 rows x 128 cols, K-chunk of 128 per blockIdx.y. 128 threads,
// micro-tile 4x8 per thread.
// ---------------------------------------------------------------------------
__global__ void gemm_atomic_kernel(const float* __restrict__ X,
                                   const float* __restrict__ W,
                                   int ldx, int sel) {
    const int KLEN = 128;
    const int KC = 32;
    __shared__ float Xs[32][KC];
    __shared__ float Wsm[KC][HD];

    float* out = sel ? g_sp : g_tp;

    int tid = threadIdx.x;       // 128 threads
    int tx = tid & 15;           // cols tx*8 .. tx*8+7
    int ty = tid >> 4;           // rows ty*4 .. ty*4+3
    int row0 = blockIdx.x * 32;
    int k0   = blockIdx.y * KLEN;

    float acc[4][8];
#pragma unroll
    for (int m = 0; m < 4; m++)
#pragma unroll
        for (int c = 0; c < 8; c++) acc[m][c] = 0.0f;

    for (int kc = 0; kc < KLEN; kc += KC) {
#pragma unroll
        for (int i = tid; i < 32 * KC; i += 128) {
            int r = i >> 5, kk = i & 31;
            Xs[r][kk] = X[(row0 + r) * ldx + (k0 + kc + kk)];
        }
#pragma unroll
        for (int i = tid; i < KC * HD; i += 128) {
            int kk = i >> 7, c = i & 127;
            Wsm[kk][c] = W[(k0 + kc + kk) * HD + c];
        }
        __syncthreads();
#pragma unroll 8
        for (int kk = 0; kk < KC; kk++) {
            float4 b0 = *reinterpret_cast<const float4*>(&Wsm[kk][tx * 8]);
            float4 b1 = *reinterpret_cast<const float4*>(&Wsm[kk][tx * 8 + 4]);
#pragma unroll
            for (int m = 0; m < 4; m++) {
                float a = Xs[ty * 4 + m][kk];
                acc[m][0] = fmaf(a, b0.x, acc[m][0]);
                acc[m][1] = fmaf(a, b0.y, acc[m][1]);
                acc[m][2] = fmaf(a, b0.z, acc[m][2]);
                acc[m][3] = fmaf(a, b0.w, acc[m][3]);
                acc[m][4] = fmaf(a, b1.x, acc[m][4]);
                acc[m][5] = fmaf(a, b1.y, acc[m][5]);
                acc[m][6] = fmaf(a, b1.z, acc[m][6]);
                acc[m][7] = fmaf(a, b1.w, acc[m][7]);
            }
        }
        __syncthreads();
    }
#pragma unroll
    for (int m = 0; m < 4; m++) {
        int row = row0 + ty * 4 + m;
#pragma unroll
        for (int c = 0; c < 8; c++)
            atomicAdd(&out[row * HD + tx * 8 + c], acc[m][c]);
    }
}

// ---------------------------------------------------------------------------
// U/V projection GEMMs: [512,128] @ [128,128] (+ b1 on the U halves).
// blockIdx.y selects {Ut, Vt, Us, Vs}. K=128 — no split, plain store.
// ---------------------------------------------------------------------------
__global__ void uv_gemm_kernel(const float* __restrict__ W1,
                               const float* __restrict__ b1) {
    const int KC = 32;
    __shared__ float Xs[32][KC];
    __shared__ float Wsm[KC][HD];

    int which = blockIdx.y;
    const float* X = (which < 2) ? g_tp : g_sp;
    const float* W = W1 + ((which & 1) ? HD * HD : 0);
    float* out = (which == 0) ? g_Ut : (which == 1) ? g_Vt
               : (which == 2) ? g_Us : g_Vs;
    bool add_bias = ((which & 1) == 0);  // b1 folded into U only

    int tid = threadIdx.x;
    int tx = tid & 15;
    int ty = tid >> 4;
    int row0 = blockIdx.x * 32;

    float acc[4][8];
#pragma unroll
    for (int m = 0; m < 4; m++)
#pragma unroll
        for (int c = 0; c < 8; c++) acc[m][c] = 0.0f;

    for (int kc = 0; kc < HD; kc += KC) {
#pragma unroll
        for (int i = tid; i < 32 * KC; i += 128) {
            int r = i >> 5, kk = i & 31;
            Xs[r][kk] = X[(row0 + r) * HD + (kc + kk)];
        }
#pragma unroll
        for (int i = tid; i < KC * HD; i += 128) {
            int kk = i >> 7, c = i & 127;
            Wsm[kk][c] = W[(kc + kk) * HD + c];
        }
        __syncthreads();
#pragma unroll 8
        for (int kk = 0; kk < KC; kk++) {
            float4 b0 = *reinterpret_cast<const float4*>(&Wsm[kk][tx * 8]);
            float4 b1v = *reinterpret_cast<const float4*>(&Wsm[kk][tx * 8 + 4]);
#pragma unroll
            for (int m = 0; m < 4; m++) {
                float a = Xs[ty * 4 + m][kk];
                acc[m][0] = fmaf(a, b0.x, acc[m][0]);
                acc[m][1] = fmaf(a, b0.y, acc[m][1]);
                acc[m][2] = fmaf(a, b0.z, acc[m][2]);
                acc[m][3] = fmaf(a, b0.w, acc[m][3]);
                acc[m][4] = fmaf(a, b1v.x, acc[m][4]);
                acc[m][5] = fmaf(a, b1v.y, acc[m][5]);
                acc[m][6] = fmaf(a, b1v.z, acc[m][6]);
                acc[m][7] = fmaf(a, b1v.w, acc[m][7]);
            }
        }
        __syncthreads();
    }
#pragma unroll
    for (int m = 0; m < 4; m++) {
        int row = row0 + ty * 4 + m;
#pragma unroll
        for (int c = 0; c < 8; c++) {
            int col = tx * 8 + c;
            float v = acc[m][c];
            if (add_bias) v += b1[col];
            out[row * HD + col] = v;
        }
    }
}

// ---------------------------------------------------------------------------
// Pairwise relation + MSE reduction.
// rel[i,j] = sigmoid(sum_h relu(U[i,h] + V[j,h]) * w2[h] + b2)  (b1 in U)
// Tile: 32(i) x 64(j) per block, 256 threads, 2x4 micro-tile.
// U/V tiles staged transposed [h][row] in smem (padded) for conflict-free
// float2/float4 reads. h processed in chunks of 32.
// ---------------------------------------------------------------------------
__global__ void pairwise_kernel(const float* __restrict__ w2,
                                const float* __restrict__ b2v,
                                float* __restrict__ out) {
    const int TI = 32, TJ = 64, HC = 32;
    const int UP = 34;  // padded stride for U tiles (floats)
    const int VP = 80;  // padded stride for V tiles (floats)

    __shared__ __align__(16) float sUt[HC * UP];
    __shared__ __align__(16) float sUs[HC * UP];
    __shared__ __align__(16) float sVt[HC * VP];
    __shared__ __align__(16) float sVs[HC * VP];
    __shared__ float sw2[HC];
    __shared__ float sred[256];

    int tid = threadIdx.x;       // 256 threads
    int tx = tid & 15;           // j = tx*4 .. +3
    int ty = tid >> 4;           // i = ty*2 .. +1
    int ibase = blockIdx.y * TI;
    int jbase = blockIdx.x * TJ;

    float accT[2][4] = {{0.f,0.f,0.f,0.f},{0.f,0.f,0.f,0.f}};
    float accS[2][4] = {{0.f,0.f,0.f,0.f},{0.f,0.f,0.f,0.f}};

    for (int hc = 0; hc < HD; hc += HC) {
        for (int i = tid; i < TI * HC; i += 256) {
            int r = i >> 5;      // row 0..31
            int h = i & 31;      // h within chunk
            sUt[h * UP + r] = g_Ut[(ibase + r) * HD + hc + h];
            sUs[h * UP + r] = g_Us[(ibase + r) * HD + hc + h];
        }
        for (int i = tid; i < TJ * HC; i += 256) {
            int r = i >> 5;      // row 0..63
            int h = i & 31;
            sVt[h * VP + r] = g_Vt[(jbase + r) * HD + hc + h];
            sVs[h * VP + r] = g_Vs[(jbase + r) * HD + hc + h];
        }
        if (tid < HC) sw2[tid] = w2[hc + tid];
        __syncthreads();

#pragma unroll 8
        for (int h = 0; h < HC; h++) {
            float wv = sw2[h];
            float2 ut = *reinterpret_cast<const float2*>(&sUt[h * UP + ty * 2]);
            float2 us = *reinterpret_cast<const float2*>(&sUs[h * UP + ty * 2]);
            float4 vt = *reinterpret_cast<const float4*>(&sVt[h * VP + tx * 4]);
            float4 vs = *reinterpret_cast<const float4*>(&sVs[h * VP + tx * 4]);
            float utv[2] = {ut.x, ut.y};
            float usv[2] = {us.x, us.y};
            float vtv[4] = {vt.x, vt.y, vt.z, vt.w};
            float vsv[4] = {vs.x, vs.y, vs.z, vs.w};
#pragma unroll
            for (int m = 0; m < 2; m++) {
#pragma unroll
                for (int n = 0; n < 4; n++) {
                    float a = fmaxf(utv[m] + vtv[n], 0.0f);
                    accT[m][n] = fmaf(a, wv, accT[m][n]);
                    float b = fmaxf(usv[m] + vsv[n], 0.0f);
                    accS[m][n] = fmaf(b, wv, accS[m][n]);
                }
            }
        }
        __syncthreads();
    }

    float b2 = b2v[0];
    float local = 0.0f;
#pragma unroll
    for (int m = 0; m < 2; m++) {
        int i = ibase + ty * 2 + m;
#pragma unroll
        for (int n = 0; n < 4; n++) {
            int j = jbase + tx * 4 + n;
            if (i == j) continue;  // diagonal zeroed in both -> diff = 0
            float rt = 1.0f / (1.0f + __expf(-(accT[m][n] + b2)));
            float rs = 1.0f / (1.0f + __expf(-(accS[m][n] + b2)));
            float d = rs - rt;
            local = fmaf(d, d, local);
        }
    }

    sred[tid] = local;
    __syncthreads();
    for (int s = 128; s > 0; s >>= 1) {
        if (tid < s) sred[tid] += sred[tid + s];
        __syncthreads();
    }
    if (tid == 0)
        atomicAdd(out, sred[0] * (1.0f / ((float)BN * (float)BN)));
}

// ---------------------------------------------------------------------------
extern "C" void kernel_launch(void* const* d_in, const int* in_sizes, int n_in,
                              void* d_out, int out_size) {
    const float* teacher = (const float*)d_in[0];  // [512, 2048]
    const float* student = (const float*)d_in[1];  // [512, 768]
    const float* Wt = (const float*)d_in[2];       // [2048, 128]
    const float* bt = (const float*)d_in[3];       // [128]
    const float* Wsw = (const float*)d_in[4];      // [768, 128]
    const float* bs = (const float*)d_in[5];       // [128]
    const float* W1 = (const float*)d_in[6];       // [256, 128]
    const float* b1 = (const float*)d_in[7];       // [128]
    const float* W2 = (const float*)d_in[8];       // [128, 1]
    const float* b2 = (const float*)d_in[9];       // [1]
    float* out = (float*)d_out;

    // 1. zero output, seed tp/sp with bias
    init_kernel<<<256, 256>>>(bt, bs, out, out_size);

    // 2. feature projections (split-K, atomic accumulate)
    gemm_atomic_kernel<<<dim3(BN / 32, TD / 128), 128>>>(teacher, Wt, TD, 0);
    gemm_atomic_kernel<<<dim3(BN / 32, SD / 128), 128>>>(student, Wsw, SD, 1);

    // 3. U/V projections through W1 halves (+b1 on U)
    uv_gemm_kernel<<<dim3(BN / 32, 4), 128>>>(W1, b1);

    // 4. pairwise relations + MSE reduction
    pairwise_kernel<<<dim3(BN / 64, BN / 32), 256>>>(W2, b2, out);
}

// round 2
// speedup vs baseline: 2.0753x; 2.0753x over previous
#include <cuda_runtime.h>
#include <math.h>

#define BN 512
#define TD 2048
#define SD 768
#define HD 128

typedef unsigned long long ull;

// Scratch (device globals — no allocations allowed)
__device__ float g_tp[BN*HD];
__device__ float g_sp[BN*HD];
__device__ float g_Ut[BN*HD];
__device__ float g_Vt[BN*HD];
__device__ float g_Us[BN*HD];
__device__ float g_Vs[BN*HD];
__device__ float g_relT[BN*BN];
__device__ float g_relS[BN*BN];

// ---- packed f32x2 helpers (sm_100+) --------------------------------------
__device__ __forceinline__ ull pk2(float a, float b) {
    ull r; asm("mov.b64 %0, {%1, %2};" : "=l"(r) : "f"(a), "f"(b)); return r;
}
__device__ __forceinline__ float2 unpk2(ull v) {
    float2 r; asm("mov.b64 {%0, %1}, %2;" : "=f"(r.x), "=f"(r.y) : "l"(v)); return r;
}
// acc += a * b (packed 2xfp32)
__device__ __forceinline__ void fma2(ull &acc, ull a, ull b) {
    asm("fma.rn.f32x2 %0, %1, %2, %0;" : "+l"(acc) : "l"(a), "l"(b));
}
// acc += relu(a + b) * w (packed 2xfp32; relu per 32-bit half)
__device__ __forceinline__ void rfma2(ull &acc, ull a, ull b, ull w) {
    asm("{\n\t"
        ".reg .b64 t;\n\t"
        ".reg .f32 tl, th;\n\t"
        "add.rn.f32x2 t, %1, %2;\n\t"
        "mov.b64 {tl, th}, t;\n\t"
        "max.f32 tl, tl, 0f00000000;\n\t"
        "max.f32 th, th, 0f00000000;\n\t"
        "mov.b64 t, {tl, th};\n\t"
        "fma.rn.f32x2 %0, t, %3, %0;\n\t"
        "}"
        : "+l"(acc) : "l"(a), "l"(b), "l"(w));
}

// ---------------------------------------------------------------------------
// Init: zero output, seed tp/sp with biases (split-K proj GEMM accumulates).
// ---------------------------------------------------------------------------
__global__ void init_kernel(const float* __restrict__ bt,
                            const float* __restrict__ bs,
                            float* __restrict__ out, int out_size) {
    int idx = blockIdx.x * blockDim.x + threadIdx.x;
    if (idx < out_size) out[idx] = 0.0f;
    if (idx < BN * HD) {
        int h = idx & (HD - 1);
        g_tp[idx] = bt[h];
        g_sp[idx] = bs[h];
    }
}

// ---------------------------------------------------------------------------
// Projection GEMM (teacher z=0, student z=1) with split-K atomic accumulate.
// Block: 32 rows x 128 cols, KLEN=128 per blockIdx.y. 128 threads, 4x8 micro
// (packed as 4x4 f32x2 pairs).
// ---------------------------------------------------------------------------
__global__ void __launch_bounds__(128)
proj_gemm(const float* __restrict__ T, const float* __restrict__ S) {
    const int KC = 32;
    __shared__ __align__(16) float Xs[32 * KC];
    __shared__ __align__(16) float Wsm[KC * HD];

    int z = blockIdx.z;
    int ky = blockIdx.y;
    const float* X;
    const float* W;
    float* out;
    int ldx;
    if (z == 0) { X = T; ldx = TD; out = g_tp; }
    else        { if (ky >= SD / 128) return; X = S; ldx = SD; out = g_sp; }
    // W pointer comes in via launch args below (use global symbol trick):
    // we pass W through the same pointer slots — see kernel_launch: Wt/Ws
    // are bound by z using the extra params.
    // (W passed as T2/S2 below)
    (void)W;
    return; // placeholder overwritten by real kernel below
}

// Real projection kernel (separate to carry the weight pointers cleanly).
__global__ void __launch_bounds__(128)
proj_gemm2(const float* __restrict__ T, const float* __restrict__ Wt,
           const float* __restrict__ S, const float* __restrict__ Ws) {
    const int KC = 32;
    __shared__ __align__(16) float Xs[32 * KC];       // [r][kk]
    __shared__ __align__(16) float Wsm[KC * HD];      // [kk][c]

    int z = blockIdx.z;
    int ky = blockIdx.y;
    const float* X; const float* W; float* out; int ldx;
    if (z == 0) { X = T; W = Wt; ldx = TD; out = g_tp; }
    else        { if (ky >= SD / 128) return; X = S; W = Ws; ldx = SD; out = g_sp; }

    int tid = threadIdx.x;        // 128
    int tx = tid & 15;            // cols tx*8..+7
    int ty = tid >> 4;            // rows ty*4..+3
    int row0 = blockIdx.x * 32;
    int k0 = ky * 128;

    ull acc[4][4];                // [m][col-pair], 8 cols = 4 pairs
#pragma unroll
    for (int m = 0; m < 4; m++)
#pragma unroll
        for (int q = 0; q < 4; q++) acc[m][q] = 0ull;

    for (int kc = 0; kc < 128; kc += KC) {
        // stage X tile 32x32 (float4 loads)
#pragma unroll
        for (int t = 0; t < 2; t++) {
            int i4 = tid + t * 128;           // 256 float4s
            int r = i4 >> 3, k4 = (i4 & 7) * 4;
            float4 v = *reinterpret_cast<const float4*>(
                &X[(row0 + r) * ldx + k0 + kc + k4]);
            *reinterpret_cast<float4*>(&Xs[r * KC + k4]) = v;
        }
        // stage W tile 32x128
#pragma unroll
        for (int t = 0; t < 8; t++) {
            int i4 = tid + t * 128;           // 1024 float4s
            int kk = i4 >> 5, c4 = (i4 & 31) * 4;
            float4 v = *reinterpret_cast<const float4*>(
                &W[(k0 + kc + kk) * HD + c4]);
            *reinterpret_cast<float4*>(&Wsm[kk * HD + c4]) = v;
        }
        __syncthreads();
#pragma unroll 8
        for (int kk = 0; kk < KC; kk++) {
            ulonglong2 b01 = *reinterpret_cast<const ulonglong2*>(&Wsm[kk * HD + tx * 8]);
            ulonglong2 b23 = *reinterpret_cast<const ulonglong2*>(&Wsm[kk * HD + tx * 8 + 4]);
#pragma unroll
            for (int m = 0; m < 4; m++) {
                float a = Xs[(ty * 4 + m) * KC + kk];
                ull ad = pk2(a, a);
                fma2(acc[m][0], ad, b01.x);
                fma2(acc[m][1], ad, b01.y);
                fma2(acc[m][2], ad, b23.x);
                fma2(acc[m][3], ad, b23.y);
            }
        }
        __syncthreads();
    }
#pragma unroll
    for (int m = 0; m < 4; m++) {
        int row = row0 + ty * 4 + m;
#pragma unroll
        for (int q = 0; q < 4; q++) {
            float2 v = unpk2(acc[m][q]);
            atomicAdd(&out[row * HD + tx * 8 + q * 2], v.x);
            atomicAdd(&out[row * HD + tx * 8 + q * 2 + 1], v.y);
        }
    }
}

// ---------------------------------------------------------------------------
// U/V projections: [512,128]@[128,128] (+b1 on U). Tile 32 rows x 64 cols,
// full K=128 (no atomics). grid (16 rowtiles, 2 coltiles, 4 mats), 128 thr,
// 4x4 micro. X staged transposed for float4 row reads.
// ---------------------------------------------------------------------------
__global__ void __launch_bounds__(128)
uv_gemm(const float* __restrict__ W1, const float* __restrict__ b1) {
    const int XP = 36;   // Xst stride (pad)
    const int WP = 68;   // Ws stride (pad)
    __shared__ __align__(16) float Xst[HD * XP];   // [k][r]
    __shared__ __align__(16) float Wsm[32 * WP];   // [kk][c]

    int which = blockIdx.z;
    const float* X = (which < 2) ? g_tp : g_sp;
    const float* W = W1 + ((which & 1) ? HD * HD : 0);
    float* out = (which == 0) ? g_Ut : (which == 1) ? g_Vt
               : (which == 2) ? g_Us : g_Vs;
    bool add_bias = ((which & 1) == 0);

    int tid = threadIdx.x;
    int tx = tid & 15;           // cols tx*4..+3
    int ty = tid >> 4;           // rows ty*4..+3
    int r0 = blockIdx.x * 32;
    int c0 = blockIdx.y * 64;

    // stage X transposed: 32 rows x 128 K
#pragma unroll
    for (int t = 0; t < 8; t++) {
        int i4 = tid + t * 128;            // 1024 float4s
        int r = i4 >> 5, k4 = (i4 & 31) * 4;
        float4 v = *reinterpret_cast<const float4*>(&X[(r0 + r) * HD + k4]);
        Xst[(k4 + 0) * XP + r] = v.x;
        Xst[(k4 + 1) * XP + r] = v.y;
        Xst[(k4 + 2) * XP + r] = v.z;
        Xst[(k4 + 3) * XP + r] = v.w;
    }

    ull acc[4][2];
#pragma unroll
    for (int m = 0; m < 4; m++) { acc[m][0] = 0ull; acc[m][1] = 0ull; }

    for (int kc = 0; kc < HD; kc += 32) {
        __syncthreads();
        // stage W chunk 32 x 64
#pragma unroll
        for (int t = 0; t < 4; t++) {
            int i4 = tid + t * 128;        // 512 float4s
            int kk = i4 >> 4, c4 = (i4 & 15) * 4;
            float4 v = *reinterpret_cast<const float4*>(&W[(kc + kk) * HD + c0 + c4]);
            *reinterpret_cast<float4*>(&Wsm[kk * WP + c4]) = v;
        }
        __syncthreads();
#pragma unroll 8
        for (int kk = 0; kk < 32; kk++) {
            int k = kc + kk;
            float4 a4 = *reinterpret_cast<const float4*>(&Xst[k * XP + ty * 4]);
            ulonglong2 bp = *reinterpret_cast<const ulonglong2*>(&Wsm[kk * WP + tx * 4]);
            ull a0 = pk2(a4.x, a4.x), a1 = pk2(a4.y, a4.y);
            ull a2 = pk2(a4.z, a4.z), a3 = pk2(a4.w, a4.w);
            fma2(acc[0][0], a0, bp.x); fma2(acc[0][1], a0, bp.y);
            fma2(acc[1][0], a1, bp.x); fma2(acc[1][1], a1, bp.y);
            fma2(acc[2][0], a2, bp.x); fma2(acc[2][1], a2, bp.y);
            fma2(acc[3][0], a3, bp.x); fma2(acc[3][1], a3, bp.y);
        }
    }

    float4 bias = make_float4(0.f, 0.f, 0.f, 0.f);
    if (add_bias) bias = *reinterpret_cast<const float4*>(&b1[c0 + tx * 4]);
#pragma unroll
    for (int m = 0; m < 4; m++) {
        float2 v0 = unpk2(acc[m][0]);
        float2 v1 = unpk2(acc[m][1]);
        float4 r = make_float4(v0.x + bias.x, v0.y + bias.y,
                               v1.x + bias.z, v1.y + bias.w);
        *reinterpret_cast<float4*>(&out[(r0 + ty * 4 + m) * HD + c0 + tx * 4]) = r;
    }
}

// ---------------------------------------------------------------------------
// Pairwise relations, one net per block (z: 0=teacher, 1=student).
// rel[i,j] = sigmoid(sum_h relu(U[i,h]+V[j,h]) * w2[h] + b2), diag zeroed.
// Tile 32(i) x 64(j), 128 threads, micro 4x4 with f32x2 packing over i-pairs.
// ---------------------------------------------------------------------------
__global__ void __launch_bounds__(128)
pairwise_net(const float* __restrict__ w2, const float* __restrict__ b2v) {
    const int HC = 32;
    const int US = 36;   // sU stride
    const int VS = 68;   // sV stride
    __shared__ __align__(16) float sU[HC * US];   // [h][i-row]
    __shared__ __align__(16) float sV[HC * VS];   // [h][j-row]
    __shared__ __align__(8)  float2 swd[HC];      // duplicated w2

    int net = blockIdx.z;
    const float* U = net ? g_Us : g_Ut;
    const float* V = net ? g_Vs : g_Vt;
    float* rel = net ? g_relS : g_relT;

    int tid = threadIdx.x;       // 128
    int tx = tid & 15;           // j = jbase + tx*4 + n
    int ty = tid >> 4;           // i = ibase + ty*4 + m
    int jbase = blockIdx.x * 64;
    int ibase = blockIdx.y * 32;

    ull acc[4][2];               // [n][i-pair]
#pragma unroll
    for (int n = 0; n < 4; n++) { acc[n][0] = 0ull; acc[n][1] = 0ull; }

    for (int hc = 0; hc < HD; hc += HC) {
        // stage U tile (32 h x 32 rows), transposed
#pragma unroll
        for (int t = 0; t < 8; t++) {
            int i = tid + t * 128;           // 1024
            int r = i >> 5, h = i & 31;
            sU[h * US + r] = U[(ibase + r) * HD + hc + h];
        }
        // stage V tile (32 h x 64 rows), transposed
#pragma unroll
        for (int t = 0; t < 16; t++) {
            int i = tid + t * 128;           // 2048
            int r = i >> 5, h = i & 31;
            sV[h * VS + r] = V[(jbase + r) * HD + hc + h];
        }
        if (tid < HC) { float w = w2[hc + tid]; swd[tid] = make_float2(w, w); }
        __syncthreads();

#pragma unroll 8
        for (int h = 0; h < HC; h++) {
            ulonglong2 up = *reinterpret_cast<const ulonglong2*>(&sU[h * US + ty * 4]);
            float4 v4 = *reinterpret_cast<const float4*>(&sV[h * VS + tx * 4]);
            ull wd = *reinterpret_cast<const ull*>(&swd[h]);
            ull vd0 = pk2(v4.x, v4.x);
            ull vd1 = pk2(v4.y, v4.y);
            ull vd2 = pk2(v4.z, v4.z);
            ull vd3 = pk2(v4.w, v4.w);
            rfma2(acc[0][0], up.x, vd0, wd); rfma2(acc[0][1], up.y, vd0, wd);
            rfma2(acc[1][0], up.x, vd1, wd); rfma2(acc[1][1], up.y, vd1, wd);
            rfma2(acc[2][0], up.x, vd2, wd); rfma2(acc[2][1], up.y, vd2, wd);
            rfma2(acc[3][0], up.x, vd3, wd); rfma2(acc[3][1], up.y, vd3, wd);
        }
        __syncthreads();
    }

    float b2 = b2v[0];
    float sums[4][4];            // [m][n]
#pragma unroll
    for (int n = 0; n < 4; n++) {
#pragma unroll
        for (int p = 0; p < 2; p++) {
            float2 v = unpk2(acc[n][p]);
            sums[p * 2 + 0][n] = v.x;
            sums[p * 2 + 1][n] = v.y;
        }
    }
#pragma unroll
    for (int m = 0; m < 4; m++) {
        int i = ibase + ty * 4 + m;
        float r[4];
#pragma unroll
        for (int n = 0; n < 4; n++) {
            float x = sums[m][n] + b2;
            r[n] = 1.0f / (1.0f + __expf(-x));
            if (i == jbase + tx * 4 + n) r[n] = 0.0f;  // diagonal
        }
        *reinterpret_cast<float4*>(&rel[i * BN + jbase + tx * 4]) =
            make_float4(r[0], r[1], r[2], r[3]);
    }
}

// ---------------------------------------------------------------------------
// Final MSE reduction over rel matrices.
// ---------------------------------------------------------------------------
__global__ void reduce_kernel(float* __restrict__ out) {
    __shared__ float sred[256];
    int idx = blockIdx.x * 256 + threadIdx.x;   // 65536 float4s total
    float4 a = reinterpret_cast<const float4*>(g_relS)[idx];
    float4 b = reinterpret_cast<const float4*>(g_relT)[idx];
    float dx = a.x - b.x, dy = a.y - b.y, dz = a.z - b.z, dw = a.w - b.w;
    float s = dx * dx + dy * dy + dz * dz + dw * dw;
    sred[threadIdx.x] = s;
    __syncthreads();
    for (int st = 128; st > 0; st >>= 1) {
        if (threadIdx.x < st) sred[threadIdx.x] += sred[threadIdx.x + st];
        __syncthreads();
    }
    if (threadIdx.x == 0)
        atomicAdd(out, sred[0] * (1.0f / ((float)BN * (float)BN)));
}

// ---------------------------------------------------------------------------
extern "C" void kernel_launch(void* const* d_in, const int* in_sizes, int n_in,
                              void* d_out, int out_size) {
    const float* teacher = (const float*)d_in[0];  // [512, 2048]
    const float* student = (const float*)d_in[1];  // [512, 768]
    const float* Wt = (const float*)d_in[2];       // [2048, 128]
    const float* bt = (const float*)d_in[3];       // [128]
    const float* Wsw = (const float*)d_in[4];      // [768, 128]
    const float* bs = (const float*)d_in[5];       // [128]
    const float* W1 = (const float*)d_in[6];       // [256, 128]
    const float* b1 = (const float*)d_in[7];       // [128]
    const float* W2 = (const float*)d_in[8];       // [128, 1]
    const float* b2 = (const float*)d_in[9];       // [1]
    float* out = (float*)d_out;

    // 1. zero output, seed tp/sp with bias
    init_kernel<<<256, 256>>>(bt, bs, out, out_size);

    // 2. feature projections (teacher z=0 uses 16 K-splits, student z=1 uses 6)
    proj_gemm2<<<dim3(16, 16, 2), 128>>>(teacher, Wt, student, Wsw);

    // 3. U/V projections through W1 halves (+b1 on U)
    uv_gemm<<<dim3(16, 2, 4), 128>>>(W1, b1);

    // 4. pairwise relations per net -> rel matrices
    pairwise_net<<<dim3(8, 16, 2), 128>>>(W2, b2);

    // 5. MSE reduction
    reduce_kernel<<<256, 256>>>(out);
}